// round 1
// baseline (speedup 1.0000x reference)
#include <cuda_runtime.h>
#include <math_constants.h>

#define NSEQ 1024
#define CH   64
#define NPTS (2 * NSEQ)

// Scratch (allocation-free rule: __device__ globals)
__device__ float g_Yi[NPTS * CH];   // y + b1   (used on the i side)
__device__ float g_Yj[NPTS * CH];   // y        (used on the j side)

// ---------------------------------------------------------------------------
// K1: y[p][o] = sum_c W1[o][c] * x[p][c];  Yi = y + b1; Yj = y
// 64 blocks x 32 points each, 256 threads.
// ---------------------------------------------------------------------------
__global__ void k1_proj(const float* __restrict__ x,
                        const float* __restrict__ w1,
                        const float* __restrict__ b1) {
    __shared__ float W1s[CH][CH + 1];  // transposed: [c][o], pad -> conflict-free
    __shared__ float xs[32][CH];
    __shared__ float b1s[CH];

    int t = threadIdx.x;
    // Stage W1 transposed. global idx = o*64 + c; store [c][o].
    for (int idx = t; idx < CH * CH; idx += 256) {
        int o = idx >> 6, c = idx & 63;
        W1s[c][o] = w1[idx];
    }
    if (t < CH) b1s[t] = b1[t];
    int p0 = blockIdx.x * 32;
    for (int idx = t; idx < 32 * CH; idx += 256) {
        xs[idx >> 6][idx & 63] = x[p0 * CH + idx];
    }
    __syncthreads();

    int o   = t & 63;
    int pl0 = t >> 6;  // 0..3
    for (int pass = 0; pass < 8; ++pass) {
        int pl = pass * 4 + pl0;
        float acc = 0.f;
#pragma unroll
        for (int c = 0; c < CH; ++c) acc += W1s[c][o] * xs[pl][c];
        int g = (p0 + pl) * CH + o;
        g_Yj[g] = acc;
        g_Yi[g] = acc + b1s[o];
    }
}

// ---------------------------------------------------------------------------
// K2: raw scores. score[i,j] = rI_i - rJ_j + sum_c w2h[c]*|Yi[i][c]-Yj[j][c]|
// Block tile 64x64, 256 threads, 4x4 microtile with strided lane mapping.
// Grid: (jt=16, it=16, b=2)
// ---------------------------------------------------------------------------
__global__ void k2_scores(const float* __restrict__ w2,
                          const float* __restrict__ b2p,
                          float* __restrict__ out) {
    __shared__ __align__(16) float Yis[64][68];  // row pad 68: 16B aligned, bank-spread
    __shared__ __align__(16) float Yjs[64][68];
    __shared__ float w2hs[CH];
    __shared__ float rIs[64], rJs[64];

    int t  = threadIdx.x;
    int jt = blockIdx.x, it = blockIdx.y, b = blockIdx.z;

    const float* Yi = g_Yi + ((b * NSEQ + it * 64) * CH);
    const float* Yj = g_Yj + ((b * NSEQ + jt * 64) * CH);

    // Stage tiles (each tile: 64 rows x 64 floats = 1024 float4)
#pragma unroll
    for (int iter = 0; iter < 4; ++iter) {
        int q   = iter * 256 + t;
        int row = q >> 4, cq = q & 15;
        float4 v = reinterpret_cast<const float4*>(Yi)[q];
        *reinterpret_cast<float4*>(&Yis[row][cq * 4]) = v;
        float4 u = reinterpret_cast<const float4*>(Yj)[q];
        *reinterpret_cast<float4*>(&Yjs[row][cq * 4]) = u;
    }
    if (t < CH) w2hs[t] = 0.5f * w2[t];
    __syncthreads();

    // Per-row scalars from the staged tiles
    if (t < 64) {
        float a = 0.f;
#pragma unroll 8
        for (int c = 0; c < CH; ++c) a += w2hs[c] * Yis[t][c];
        rIs[t] = a + b2p[0];
    } else if (t < 128) {
        int j = t - 64;
        float a = 0.f;
#pragma unroll 8
        for (int c = 0; c < CH; ++c) a += w2hs[c] * Yjs[j][c];
        rJs[j] = a;
    }
    __syncthreads();

    int tx = t & 15, ty = t >> 4;   // i_local = ty + 16r, j_local = tx + 16s
    float acc[4][4] = {};

#pragma unroll
    for (int c = 0; c < CH; c += 4) {
        float4 w4 = *reinterpret_cast<const float4*>(&w2hs[c]);
        float4 yi[4], yj[4];
#pragma unroll
        for (int r = 0; r < 4; ++r)
            yi[r] = *reinterpret_cast<const float4*>(&Yis[ty + 16 * r][c]);
#pragma unroll
        for (int s = 0; s < 4; ++s)
            yj[s] = *reinterpret_cast<const float4*>(&Yjs[tx + 16 * s][c]);
#pragma unroll
        for (int r = 0; r < 4; ++r)
#pragma unroll
            for (int s = 0; s < 4; ++s) {
                acc[r][s] += w4.x * fabsf(yi[r].x - yj[s].x);
                acc[r][s] += w4.y * fabsf(yi[r].y - yj[s].y);
                acc[r][s] += w4.z * fabsf(yi[r].z - yj[s].z);
                acc[r][s] += w4.w * fabsf(yi[r].w - yj[s].w);
            }
    }

#pragma unroll
    for (int r = 0; r < 4; ++r) {
        int ig   = it * 64 + ty + 16 * r;
        float ri = rIs[ty + 16 * r];
        float* orow = out + (size_t)(b * NSEQ + ig) * NSEQ + jt * 64;
#pragma unroll
        for (int s = 0; s < 4; ++s) {
            orow[tx + 16 * s] = ri - rJs[tx + 16 * s] + acc[r][s];
        }
    }
}

// ---------------------------------------------------------------------------
// K3: in-place row softmax over j. One block per (b,i) row. 256 threads x 4.
// ---------------------------------------------------------------------------
__global__ void k3_softmax(float* __restrict__ out) {
    __shared__ float red[8];
    __shared__ float bcast;
    size_t base = (size_t)blockIdx.x * NSEQ;
    int t = threadIdx.x;

    float v0 = out[base + t];
    float v1 = out[base + t + 256];
    float v2 = out[base + t + 512];
    float v3 = out[base + t + 768];

    float m = fmaxf(fmaxf(v0, v1), fmaxf(v2, v3));
#pragma unroll
    for (int o = 16; o; o >>= 1) m = fmaxf(m, __shfl_xor_sync(0xffffffffu, m, o));
    if ((t & 31) == 0) red[t >> 5] = m;
    __syncthreads();
    if (t == 0) {
        float mm = red[0];
#pragma unroll
        for (int i = 1; i < 8; ++i) mm = fmaxf(mm, red[i]);
        bcast = mm;
    }
    __syncthreads();
    m = bcast;

    float e0 = __expf(v0 - m), e1 = __expf(v1 - m);
    float e2 = __expf(v2 - m), e3 = __expf(v3 - m);
    float s = (e0 + e1) + (e2 + e3);
#pragma unroll
    for (int o = 16; o; o >>= 1) s += __shfl_xor_sync(0xffffffffu, s, o);
    __syncthreads();  // protect red reuse
    if ((t & 31) == 0) red[t >> 5] = s;
    __syncthreads();
    if (t == 0) {
        float ss = red[0];
#pragma unroll
        for (int i = 1; i < 8; ++i) ss += red[i];
        bcast = 1.0f / ss;
    }
    __syncthreads();
    float inv = bcast;

    out[base + t]       = e0 * inv;
    out[base + t + 256] = e1 * inv;
    out[base + t + 512] = e2 * inv;
    out[base + t + 768] = e3 * inv;
}

// ---------------------------------------------------------------------------
extern "C" void kernel_launch(void* const* d_in, const int* in_sizes, int n_in,
                              void* d_out, int out_size) {
    const float* x  = (const float*)d_in[0];  // [2,1024,64]
    const float* w1 = (const float*)d_in[1];  // [64,64]
    const float* b1 = (const float*)d_in[2];  // [64]
    const float* w2 = (const float*)d_in[3];  // [64]
    const float* b2 = (const float*)d_in[4];  // scalar
    float* out = (float*)d_out;               // [2,1024,1024]

    k1_proj<<<64, 256>>>(x, w1, b1);
    dim3 g2(16, 16, 2);
    k2_scores<<<g2, 256>>>(w2, b2, out);
    k3_softmax<<<2048, 256>>>(out);
}

// round 2
// speedup vs baseline: 1.0218x; 1.0218x over previous
#include <cuda_runtime.h>

#define NSEQ 1024
#define CH   64
#define NPTS (2 * NSEQ)

typedef unsigned long long u64;

// Scratch (allocation-free rule: __device__ globals)
__device__ float g_Yi[NPTS * CH];   // y + b1     (i side)
__device__ float g_Yj[NPTS * CH];   // -y         (j side, pre-negated)

// Packed f32x2 helpers (Blackwell FADD2 / FFMA2)
__device__ __forceinline__ u64 add2(u64 a, u64 b) {
    u64 r; asm("add.rn.f32x2 %0, %1, %2;" : "=l"(r) : "l"(a), "l"(b)); return r;
}
__device__ __forceinline__ u64 fma2(u64 a, u64 b, u64 c) {
    u64 r; asm("fma.rn.f32x2 %0, %1, %2, %3;" : "=l"(r) : "l"(a), "l"(b), "l"(c)); return r;
}
#define ABS2(a) ((a) & 0x7fffffff7fffffffULL)

// ---------------------------------------------------------------------------
// K1: y[p][o] = sum_c W1[o][c] * x[p][c];  Yi = y + b1; Yj = -y
// 512 blocks x 4 points, 256 threads (o = t&63, pl = t>>6).
// ---------------------------------------------------------------------------
__global__ void k1_proj(const float* __restrict__ x,
                        const float* __restrict__ w1,
                        const float* __restrict__ b1) {
    __shared__ __align__(16) float W1s[CH][68];  // [o][c], padded rows
    __shared__ __align__(16) float xs[4][CH];
    __shared__ float b1s[CH];

    int t = threadIdx.x;
    // Stage W1 [o][c] row-major with float4 (1024 float4s / 256 threads)
#pragma unroll
    for (int q = t; q < 1024; q += 256) {
        float4 v = reinterpret_cast<const float4*>(w1)[q];
        *reinterpret_cast<float4*>(&W1s[q >> 4][(q & 15) * 4]) = v;
    }
    if (t < CH) b1s[t] = b1[t];
    int p0 = blockIdx.x * 4;
    if (t < 64) {  // 4 rows x 64 floats = 64 float4
        float4 v = reinterpret_cast<const float4*>(x + p0 * CH)[t];
        *reinterpret_cast<float4*>(&xs[t >> 4][(t & 15) * 4]) = v;
    }
    __syncthreads();

    int o = t & 63, pl = t >> 6;
    float acc = 0.f;
#pragma unroll
    for (int c = 0; c < CH; c += 4) {
        float4 wv = *reinterpret_cast<const float4*>(&W1s[o][c]);
        float4 xv = *reinterpret_cast<const float4*>(&xs[pl][c]);
        acc += wv.x * xv.x;
        acc += wv.y * xv.y;
        acc += wv.z * xv.z;
        acc += wv.w * xv.w;
    }
    int g = (p0 + pl) * CH + o;
    g_Yj[g] = -acc;
    g_Yi[g] = acc + b1s[o];
}

// ---------------------------------------------------------------------------
// K2: raw scores. score[i,j] = rI_i + rJn_j + sum_c w2h[c]*|Yi[i][c]+Yjn[j][c]|
// (Yjn is pre-negated, so the pairwise sub is an ADD2.)
// Block tile 64x64, 256 threads, 4x4 microtile, packed f32x2 math.
// Grid: (jt=16, it=16, b=2)
// ---------------------------------------------------------------------------
__global__ void __launch_bounds__(256, 2)
k2_scores(const float* __restrict__ w2,
          const float* __restrict__ b2p,
          float* __restrict__ out) {
    __shared__ __align__(16) float Yis[64][68];
    __shared__ __align__(16) float Yjs[64][68];
    __shared__ __align__(16) float w2hs[CH];
    __shared__ float rIs[64], rJn[64];

    int t  = threadIdx.x;
    int jt = blockIdx.x, it = blockIdx.y, b = blockIdx.z;

    const float* Yi = g_Yi + ((b * NSEQ + it * 64) * CH);
    const float* Yj = g_Yj + ((b * NSEQ + jt * 64) * CH);

#pragma unroll
    for (int iter = 0; iter < 4; ++iter) {
        int q   = iter * 256 + t;
        int row = q >> 4, cq = (q & 15) * 4;
        float4 v = reinterpret_cast<const float4*>(Yi)[q];
        *reinterpret_cast<float4*>(&Yis[row][cq]) = v;
        float4 u = reinterpret_cast<const float4*>(Yj)[q];
        *reinterpret_cast<float4*>(&Yjs[row][cq]) = u;
    }
    if (t < CH) w2hs[t] = 0.5f * w2[t];
    __syncthreads();

    // Per-row scalars from staged tiles
    if (t < 64) {
        float a = 0.f;
#pragma unroll 8
        for (int c = 0; c < CH; ++c) a += w2hs[c] * Yis[t][c];
        rIs[t] = a + b2p[0];
    } else if (t < 128) {
        int j = t - 64;
        float a = 0.f;
#pragma unroll 8
        for (int c = 0; c < CH; ++c) a += w2hs[c] * Yjs[j][c];
        rJn[j] = a;  // already negated values -> rJn = -rJ
    }
    __syncthreads();

    int tx = t & 15, ty = t >> 4;   // i_local = ty + 16r, j_local = tx + 16s
    u64 acc[4][4] = {};             // packed f32x2 accumulators

#pragma unroll
    for (int c = 0; c < CH; c += 4) {
        ulonglong2 w = *reinterpret_cast<const ulonglong2*>(&w2hs[c]);
        ulonglong2 yi[4], yj[4];
#pragma unroll
        for (int r = 0; r < 4; ++r)
            yi[r] = *reinterpret_cast<const ulonglong2*>(&Yis[ty + 16 * r][c]);
#pragma unroll
        for (int s = 0; s < 4; ++s)
            yj[s] = *reinterpret_cast<const ulonglong2*>(&Yjs[tx + 16 * s][c]);
#pragma unroll
        for (int r = 0; r < 4; ++r)
#pragma unroll
            for (int s = 0; s < 4; ++s) {
                acc[r][s] = fma2(w.x, ABS2(add2(yi[r].x, yj[s].x)), acc[r][s]);
                acc[r][s] = fma2(w.y, ABS2(add2(yi[r].y, yj[s].y)), acc[r][s]);
            }
    }

#pragma unroll
    for (int r = 0; r < 4; ++r) {
        int ig   = it * 64 + ty + 16 * r;
        float ri = rIs[ty + 16 * r];
        float* orow = out + (size_t)(b * NSEQ + ig) * NSEQ + jt * 64;
#pragma unroll
        for (int s = 0; s < 4; ++s) {
            u64 a = acc[r][s];
            float lo = __uint_as_float((unsigned)a);
            float hi = __uint_as_float((unsigned)(a >> 32));
            orow[tx + 16 * s] = ri + rJn[tx + 16 * s] + (lo + hi);
        }
    }
}

// ---------------------------------------------------------------------------
// K3: in-place row softmax over j. One block per (b,i) row. 256 threads x 4.
// ---------------------------------------------------------------------------
__global__ void k3_softmax(float* __restrict__ out) {
    __shared__ float red[8];
    __shared__ float bcast;
    size_t base = (size_t)blockIdx.x * NSEQ;
    int t = threadIdx.x;

    float v0 = out[base + t];
    float v1 = out[base + t + 256];
    float v2 = out[base + t + 512];
    float v3 = out[base + t + 768];

    float m = fmaxf(fmaxf(v0, v1), fmaxf(v2, v3));
#pragma unroll
    for (int o = 16; o; o >>= 1) m = fmaxf(m, __shfl_xor_sync(0xffffffffu, m, o));
    if ((t & 31) == 0) red[t >> 5] = m;
    __syncthreads();
    if (t == 0) {
        float mm = red[0];
#pragma unroll
        for (int i = 1; i < 8; ++i) mm = fmaxf(mm, red[i]);
        bcast = mm;
    }
    __syncthreads();
    m = bcast;

    float e0 = __expf(v0 - m), e1 = __expf(v1 - m);
    float e2 = __expf(v2 - m), e3 = __expf(v3 - m);
    float s = (e0 + e1) + (e2 + e3);
#pragma unroll
    for (int o = 16; o; o >>= 1) s += __shfl_xor_sync(0xffffffffu, s, o);
    __syncthreads();
    if ((t & 31) == 0) red[t >> 5] = s;
    __syncthreads();
    if (t == 0) {
        float ss = red[0];
#pragma unroll
        for (int i = 1; i < 8; ++i) ss += red[i];
        bcast = 1.0f / ss;
    }
    __syncthreads();
    float inv = bcast;

    out[base + t]       = e0 * inv;
    out[base + t + 256] = e1 * inv;
    out[base + t + 512] = e2 * inv;
    out[base + t + 768] = e3 * inv;
}

// ---------------------------------------------------------------------------
extern "C" void kernel_launch(void* const* d_in, const int* in_sizes, int n_in,
                              void* d_out, int out_size) {
    const float* x  = (const float*)d_in[0];  // [2,1024,64]
    const float* w1 = (const float*)d_in[1];  // [64,64]
    const float* b1 = (const float*)d_in[2];  // [64]
    const float* w2 = (const float*)d_in[3];  // [64]
    const float* b2 = (const float*)d_in[4];  // scalar
    float* out = (float*)d_out;               // [2,1024,1024]

    k1_proj<<<512, 256>>>(x, w1, b1);
    dim3 g2(16, 16, 2);
    k2_scores<<<g2, 256>>>(w2, b2, out);
    k3_softmax<<<2048, 256>>>(out);
}

// round 3
// speedup vs baseline: 1.1851x; 1.1599x over previous
#include <cuda_runtime.h>

#define NSEQ 1024
#define CH   64
#define NPTS (2 * NSEQ)

// Scratch (allocation-free rule: __device__ globals)
__device__ float g_Yi[NPTS * CH];   // y + b1   (i side)
__device__ float g_Yj[NPTS * CH];   // -y       (j side, pre-negated)

// ---------------------------------------------------------------------------
// K1: y[p][o] = sum_c W1[o][c] * x[p][c];  Yi = y + b1; Yj = -y
// 128 blocks x 16 points, 256 threads. Thread: o = t&63, point-group pg = t>>6
// (4 points each). W1 staged transposed [c][o] (conflict-free per-c reads),
// x staged transposed [c][p] (float4 over the 4 points).
// ---------------------------------------------------------------------------
__global__ void k1_proj(const float* __restrict__ x,
                        const float* __restrict__ w1,
                        const float* __restrict__ b1) {
    __shared__ float W1T[CH][65];                  // [c][o]
    __shared__ __align__(16) float xsT[CH][20];    // [c][p], pad 20 (16B-mult)
    __shared__ float b1s[CH];

    int t = threadIdx.x;
    int p0 = blockIdx.x * 16;

    // Stage W1 transposed: 1024 float4s, 4 per thread
#pragma unroll
    for (int q = t; q < 1024; q += 256) {
        int o = q >> 4, c4 = (q & 15) * 4;
        float4 v = reinterpret_cast<const float4*>(w1)[q];
        W1T[c4 + 0][o] = v.x;
        W1T[c4 + 1][o] = v.y;
        W1T[c4 + 2][o] = v.z;
        W1T[c4 + 3][o] = v.w;
    }
    // Stage x transposed: 16 points x 64 ch = 256 float4s, 1 per thread
    {
        int pl = t >> 4, c4 = (t & 15) * 4;
        float4 v = reinterpret_cast<const float4*>(x + p0 * CH)[t];
        xsT[c4 + 0][pl] = v.x;
        xsT[c4 + 1][pl] = v.y;
        xsT[c4 + 2][pl] = v.z;
        xsT[c4 + 3][pl] = v.w;
    }
    if (t < CH) b1s[t] = b1[t];
    __syncthreads();

    int o = t & 63, pg = t >> 6;
    float a0 = 0.f, a1 = 0.f, a2 = 0.f, a3 = 0.f;
#pragma unroll
    for (int c = 0; c < CH; ++c) {
        float wv = W1T[c][o];
        float4 xv = *reinterpret_cast<const float4*>(&xsT[c][pg * 4]);
        a0 += wv * xv.x;
        a1 += wv * xv.y;
        a2 += wv * xv.z;
        a3 += wv * xv.w;
    }

    float b1v = b1s[o];
    int pbase = p0 + pg * 4;
    g_Yj[(pbase + 0) * CH + o] = -a0;  g_Yi[(pbase + 0) * CH + o] = a0 + b1v;
    g_Yj[(pbase + 1) * CH + o] = -a1;  g_Yi[(pbase + 1) * CH + o] = a1 + b1v;
    g_Yj[(pbase + 2) * CH + o] = -a2;  g_Yi[(pbase + 2) * CH + o] = a2 + b1v;
    g_Yj[(pbase + 3) * CH + o] = -a3;  g_Yi[(pbase + 3) * CH + o] = a3 + b1v;
}

// ---------------------------------------------------------------------------
// K2: raw scores. score[i,j] = rI_i + rJn_j + sum_c w2h[c]*|Yi[i][c]+Yjn[j][c]|
// (Yjn pre-negated, so the pairwise sub is an add.)
// Block tile 64x64, 256 threads, 4x4 microtile (scalar fp32 — proven fastest).
// Grid: (jt=16, it=16, b=2)
// ---------------------------------------------------------------------------
__global__ void k2_scores(const float* __restrict__ w2,
                          const float* __restrict__ b2p,
                          float* __restrict__ out) {
    __shared__ __align__(16) float Yis[64][68];
    __shared__ __align__(16) float Yjs[64][68];
    __shared__ float w2hs[CH];
    __shared__ float rIs[64], rJn[64];

    int t  = threadIdx.x;
    int jt = blockIdx.x, it = blockIdx.y, b = blockIdx.z;

    const float* Yi = g_Yi + ((b * NSEQ + it * 64) * CH);
    const float* Yj = g_Yj + ((b * NSEQ + jt * 64) * CH);

#pragma unroll
    for (int iter = 0; iter < 4; ++iter) {
        int q   = iter * 256 + t;
        int row = q >> 4, cq = (q & 15) * 4;
        float4 v = reinterpret_cast<const float4*>(Yi)[q];
        *reinterpret_cast<float4*>(&Yis[row][cq]) = v;
        float4 u = reinterpret_cast<const float4*>(Yj)[q];
        *reinterpret_cast<float4*>(&Yjs[row][cq]) = u;
    }
    if (t < CH) w2hs[t] = 0.5f * w2[t];
    __syncthreads();

    // Per-row scalars from staged tiles
    if (t < 64) {
        float a = 0.f;
#pragma unroll 8
        for (int c = 0; c < CH; ++c) a += w2hs[c] * Yis[t][c];
        rIs[t] = a + b2p[0];
    } else if (t < 128) {
        int j = t - 64;
        float a = 0.f;
#pragma unroll 8
        for (int c = 0; c < CH; ++c) a += w2hs[c] * Yjs[j][c];
        rJn[j] = a;  // Yjs holds -y, so this is already -rJ
    }
    __syncthreads();

    int tx = t & 15, ty = t >> 4;   // i_local = ty + 16r, j_local = tx + 16s
    float acc[4][4] = {};

#pragma unroll
    for (int c = 0; c < CH; c += 4) {
        float4 w4 = *reinterpret_cast<const float4*>(&w2hs[c]);
        float4 yi[4], yj[4];
#pragma unroll
        for (int r = 0; r < 4; ++r)
            yi[r] = *reinterpret_cast<const float4*>(&Yis[ty + 16 * r][c]);
#pragma unroll
        for (int s = 0; s < 4; ++s)
            yj[s] = *reinterpret_cast<const float4*>(&Yjs[tx + 16 * s][c]);
#pragma unroll
        for (int r = 0; r < 4; ++r)
#pragma unroll
            for (int s = 0; s < 4; ++s) {
                acc[r][s] += w4.x * fabsf(yi[r].x + yj[s].x);
                acc[r][s] += w4.y * fabsf(yi[r].y + yj[s].y);
                acc[r][s] += w4.z * fabsf(yi[r].z + yj[s].z);
                acc[r][s] += w4.w * fabsf(yi[r].w + yj[s].w);
            }
    }

#pragma unroll
    for (int r = 0; r < 4; ++r) {
        int ig   = it * 64 + ty + 16 * r;
        float ri = rIs[ty + 16 * r];
        float* orow = out + (size_t)(b * NSEQ + ig) * NSEQ + jt * 64;
#pragma unroll
        for (int s = 0; s < 4; ++s) {
            orow[tx + 16 * s] = ri + rJn[tx + 16 * s] + acc[r][s];
        }
    }
}

// ---------------------------------------------------------------------------
// K3: in-place row softmax over j. One block per (b,i) row. 256 threads x 4.
// ---------------------------------------------------------------------------
__global__ void k3_softmax(float* __restrict__ out) {
    __shared__ float red[8];
    __shared__ float bcast;
    size_t base = (size_t)blockIdx.x * NSEQ;
    int t = threadIdx.x;

    float v0 = out[base + t];
    float v1 = out[base + t + 256];
    float v2 = out[base + t + 512];
    float v3 = out[base + t + 768];

    float m = fmaxf(fmaxf(v0, v1), fmaxf(v2, v3));
#pragma unroll
    for (int o = 16; o; o >>= 1) m = fmaxf(m, __shfl_xor_sync(0xffffffffu, m, o));
    if ((t & 31) == 0) red[t >> 5] = m;
    __syncthreads();
    if (t == 0) {
        float mm = red[0];
#pragma unroll
        for (int i = 1; i < 8; ++i) mm = fmaxf(mm, red[i]);
        bcast = mm;
    }
    __syncthreads();
    m = bcast;

    float e0 = __expf(v0 - m), e1 = __expf(v1 - m);
    float e2 = __expf(v2 - m), e3 = __expf(v3 - m);
    float s = (e0 + e1) + (e2 + e3);
#pragma unroll
    for (int o = 16; o; o >>= 1) s += __shfl_xor_sync(0xffffffffu, s, o);
    __syncthreads();
    if ((t & 31) == 0) red[t >> 5] = s;
    __syncthreads();
    if (t == 0) {
        float ss = red[0];
#pragma unroll
        for (int i = 1; i < 8; ++i) ss += red[i];
        bcast = 1.0f / ss;
    }
    __syncthreads();
    float inv = bcast;

    out[base + t]       = e0 * inv;
    out[base + t + 256] = e1 * inv;
    out[base + t + 512] = e2 * inv;
    out[base + t + 768] = e3 * inv;
}

// ---------------------------------------------------------------------------
extern "C" void kernel_launch(void* const* d_in, const int* in_sizes, int n_in,
                              void* d_out, int out_size) {
    const float* x  = (const float*)d_in[0];  // [2,1024,64]
    const float* w1 = (const float*)d_in[1];  // [64,64]
    const float* b1 = (const float*)d_in[2];  // [64]
    const float* w2 = (const float*)d_in[3];  // [64]
    const float* b2 = (const float*)d_in[4];  // scalar
    float* out = (float*)d_out;               // [2,1024,1024]

    k1_proj<<<128, 256>>>(x, w1, b1);
    dim3 g2(16, 16, 2);
    k2_scores<<<g2, 256>>>(w2, b2, out);
    k3_softmax<<<2048, 256>>>(out);
}